// round 1
// baseline (speedup 1.0000x reference)
#include <cuda_runtime.h>
#include <math.h>

#define N_NODES 50000
#define N_EDGES 800000
#define NFEAT   512
#define NHID    128
#define NCLASS  64

// Scratch (allocation-free): h0 = X@W1, h1 = relu(A@h0 + b1), h2 reuses g_h0.
__device__ float g_h0[(size_t)N_NODES * NHID];
__device__ float g_h1[(size_t)N_NODES * NHID];

// ---------------------------------------------------------------------------
// GEMM1: out[50000,128] = x[50000,512] @ W1[512,128]
// Block tile 64x128 (full N), BK=16, 256 threads, thread tile 4x8.
// ---------------------------------------------------------------------------
__global__ __launch_bounds__(256) void gemm1_kernel(const float* __restrict__ x,
                                                    const float* __restrict__ W1,
                                                    float* __restrict__ out)
{
    __shared__ float As[64][16];    // [m][k]
    __shared__ float Bs[16][128];   // [k][n]

    const int tid = threadIdx.x;
    const int tx  = tid & 15;       // col group (x8)
    const int ty  = tid >> 4;       // row group (x4)
    const int blockM = blockIdx.x * 64;

    float acc[4][8];
#pragma unroll
    for (int i = 0; i < 4; i++)
#pragma unroll
        for (int j = 0; j < 8; j++) acc[i][j] = 0.0f;

    // load indices
    const int lm  = tid >> 2;            // 0..63   (row within A tile)
    const int lkq = (tid & 3) * 4;       // 0,4,8,12 (k quad within A tile)
    int mg = blockM + lm;
    if (mg >= N_NODES) mg = N_NODES - 1; // clamp (stores are guarded)

    for (int k0 = 0; k0 < NFEAT; k0 += 16) {
        // A tile: 64x16, one float4 per thread
        float4 av = *(const float4*)(x + (size_t)mg * NFEAT + k0 + lkq);
        *(float4*)&As[lm][lkq] = av;

        // B tile: 16x128, two float4 per thread
#pragma unroll
        for (int r = 0; r < 2; r++) {
            int idx = tid + r * 256;         // 0..511
            int bk = idx >> 5;               // 0..15
            int bc = (idx & 31) * 4;         // 0..124
            float4 bv = *(const float4*)(W1 + (size_t)(k0 + bk) * NHID + bc);
            *(float4*)&Bs[bk][bc] = bv;
        }
        __syncthreads();

#pragma unroll
        for (int kk = 0; kk < 16; kk++) {
            float a[4];
#pragma unroll
            for (int i = 0; i < 4; i++) a[i] = As[ty * 4 + i][kk];
            float b[8];
            *(float4*)&b[0] = *(const float4*)&Bs[kk][tx * 8];
            *(float4*)&b[4] = *(const float4*)&Bs[kk][tx * 8 + 4];
#pragma unroll
            for (int i = 0; i < 4; i++)
#pragma unroll
                for (int j = 0; j < 8; j++)
                    acc[i][j] = fmaf(a[i], b[j], acc[i][j]);
        }
        __syncthreads();
    }

    // epilogue
#pragma unroll
    for (int i = 0; i < 4; i++) {
        int row = blockM + ty * 4 + i;
        if (row < N_NODES) {
            float* p = out + (size_t)row * NHID + tx * 8;
            *(float4*)p       = make_float4(acc[i][0], acc[i][1], acc[i][2], acc[i][3]);
            *(float4*)(p + 4) = make_float4(acc[i][4], acc[i][5], acc[i][6], acc[i][7]);
        }
    }
}

// ---------------------------------------------------------------------------
// SpMM: hout[r,:] = sum_{e in row r} vals[e] * hin[cols[e],:]   (+bias, relu)
// Warp per output row; rows[] is sorted -> binary-search the edge range.
// Lane owns 4 contiguous features (float4 gather per edge).
// ---------------------------------------------------------------------------
template <bool RELU>
__global__ __launch_bounds__(256) void spmm_kernel(const int* __restrict__ rows,
                                                   const int* __restrict__ cols,
                                                   const float* __restrict__ vals,
                                                   const float* __restrict__ hin,
                                                   const float* __restrict__ bias,
                                                   float* __restrict__ hout)
{
    const int gw   = (blockIdx.x * blockDim.x + threadIdx.x) >> 5;
    const int lane = threadIdx.x & 31;
    if (gw >= N_NODES) return;

    // lower_bound(rows, gw) and lower_bound(rows, gw+1); warp-uniform
    int lo = 0, hi = N_EDGES;
    while (lo < hi) { int mid = (lo + hi) >> 1; if (rows[mid] < gw) lo = mid + 1; else hi = mid; }
    const int start = lo;
    hi = N_EDGES;
    while (lo < hi) { int mid = (lo + hi) >> 1; if (rows[mid] < gw + 1) lo = mid + 1; else hi = mid; }
    const int end = lo;

    float ax = 0.f, ay = 0.f, az = 0.f, aw = 0.f;

    int e = start;
    for (; e + 2 <= end; e += 2) {
        int   c0 = cols[e],  c1 = cols[e + 1];
        float v0 = vals[e],  v1 = vals[e + 1];
        float4 h0 = *(const float4*)(hin + (size_t)c0 * NHID + lane * 4);
        float4 h1 = *(const float4*)(hin + (size_t)c1 * NHID + lane * 4);
        ax = fmaf(v0, h0.x, ax); ay = fmaf(v0, h0.y, ay);
        az = fmaf(v0, h0.z, az); aw = fmaf(v0, h0.w, aw);
        ax = fmaf(v1, h1.x, ax); ay = fmaf(v1, h1.y, ay);
        az = fmaf(v1, h1.z, az); aw = fmaf(v1, h1.w, aw);
    }
    if (e < end) {
        int   c0 = cols[e];
        float v0 = vals[e];
        float4 h0 = *(const float4*)(hin + (size_t)c0 * NHID + lane * 4);
        ax = fmaf(v0, h0.x, ax); ay = fmaf(v0, h0.y, ay);
        az = fmaf(v0, h0.z, az); aw = fmaf(v0, h0.w, aw);
    }

    if (RELU) {
        float4 b = ((const float4*)bias)[lane];
        ax = fmaxf(ax + b.x, 0.f); ay = fmaxf(ay + b.y, 0.f);
        az = fmaxf(az + b.z, 0.f); aw = fmaxf(aw + b.w, 0.f);
    }
    *(float4*)(hout + (size_t)gw * NHID + lane * 4) = make_float4(ax, ay, az, aw);
}

// ---------------------------------------------------------------------------
// GEMM2 + log_softmax: out[r,:] = logsoftmax(h[r,:] @ W2 + b2)
// 8 warps/block, warp per row; W2 (128x64) staged in SMEM.
// ---------------------------------------------------------------------------
__global__ __launch_bounds__(256) void gemm2_softmax_kernel(const float* __restrict__ h,
                                                            const float* __restrict__ W2,
                                                            const float* __restrict__ b2,
                                                            float* __restrict__ out)
{
    __shared__ float sW[NHID * NCLASS];   // 32 KB
    __shared__ float sb[NCLASS];
    __shared__ float srow[8][NHID];       // 4 KB

    const int tid = threadIdx.x;
    for (int i = tid; i < NHID * NCLASS / 4; i += 256)
        ((float4*)sW)[i] = ((const float4*)W2)[i];
    if (tid < NCLASS) sb[tid] = b2[tid];
    __syncthreads();

    const int warp = tid >> 5;
    const int lane = tid & 31;
    const int row  = blockIdx.x * 8 + warp;
    if (row >= N_NODES) return;

    ((float4*)srow[warp])[lane] = ((const float4*)(h + (size_t)row * NHID))[lane];
    __syncwarp();

    float a0 = sb[lane], a1 = sb[lane + 32];
#pragma unroll 4
    for (int k = 0; k < NHID; k++) {
        float hk = srow[warp][k];
        a0 = fmaf(hk, sW[k * NCLASS + lane],      a0);
        a1 = fmaf(hk, sW[k * NCLASS + lane + 32], a1);
    }

    float m = fmaxf(a0, a1);
#pragma unroll
    for (int o = 16; o; o >>= 1) m = fmaxf(m, __shfl_xor_sync(0xffffffffu, m, o));
    float s = expf(a0 - m) + expf(a1 - m);
#pragma unroll
    for (int o = 16; o; o >>= 1) s += __shfl_xor_sync(0xffffffffu, s, o);
    const float lse = m + logf(s);

    out[(size_t)row * NCLASS + lane]      = a0 - lse;
    out[(size_t)row * NCLASS + lane + 32] = a1 - lse;
}

// ---------------------------------------------------------------------------
extern "C" void kernel_launch(void* const* d_in, const int* in_sizes, int n_in,
                              void* d_out, int out_size)
{
    const float* x    = (const float*)d_in[0];
    const int*   rows = (const int*)  d_in[1];
    const int*   cols = (const int*)  d_in[2];
    const float* vals = (const float*)d_in[3];
    const float* W1   = (const float*)d_in[4];
    const float* b1   = (const float*)d_in[5];
    const float* W2   = (const float*)d_in[6];
    const float* b2   = (const float*)d_in[7];
    float* out = (float*)d_out;

    float *h0, *h1;
    cudaGetSymbolAddress((void**)&h0, g_h0);
    cudaGetSymbolAddress((void**)&h1, g_h1);

    // 1) h0 = X @ W1
    gemm1_kernel<<<(N_NODES + 63) / 64, 256>>>(x, W1, h0);

    // 2) h1 = relu(A @ h0 + b1)
    const int spmm_blocks = (N_NODES * 32 + 255) / 256;
    spmm_kernel<true><<<spmm_blocks, 256>>>(rows, cols, vals, h0, b1, h1);

    // 3) h0 <- A @ h1   (reuse buffer)
    spmm_kernel<false><<<spmm_blocks, 256>>>(rows, cols, vals, h1, b1, h0);

    // 4) out = logsoftmax(h0 @ W2 + b2)
    gemm2_softmax_kernel<<<(N_NODES + 7) / 8, 256>>>(h0, W2, b2, out);
}

// round 3
// speedup vs baseline: 1.1267x; 1.1267x over previous
#include <cuda_runtime.h>
#include <math.h>
#include <stdint.h>

#define N_NODES 50000
#define N_EDGES 800000
#define NFEAT   512
#define NHID    128
#define NCLASS  64

// Scratch (allocation-free)
__device__ float g_h0[(size_t)N_NODES * NHID];
__device__ float g_h1[(size_t)N_NODES * NHID];

// Packed fp32x2 helpers (sm_100-family base feature; valid at compute_103)
#define FMA2(acc, a, b) \
    asm("fma.rn.f32x2 %0, %1, %2, %0;" : "+l"(acc) : "l"(a), "l"(b))
#define PACK2(out, lo, hi) \
    asm("mov.b64 %0, {%1, %2};" : "=l"(out) : "r"(lo), "r"(hi))
#define UNPACK2(lo, hi, in) \
    asm("mov.b64 {%0, %1}, %2;" : "=r"(lo), "=r"(hi) : "l"(in))

// ---------------------------------------------------------------------------
// GEMM1: out[50000,128] = x[50000,512] @ W1[512,128]
// Block tile 64x128 (full N), BK=16, 256 threads, thread tile 4x8 via f32x2.
// ---------------------------------------------------------------------------
__global__ __launch_bounds__(256) void gemm1_kernel(const float* __restrict__ x,
                                                    const float* __restrict__ W1,
                                                    float* __restrict__ out)
{
    __shared__ float As[16][68];    // [k][m] transposed, pad 68
    __shared__ float Bs[16][128];   // [k][n]

    const int tid = threadIdx.x;
    const int tx  = tid & 15;       // col group (8 cols = 4 pairs)
    const int ty  = tid >> 4;       // row group (4 rows)
    const int blockM = blockIdx.x * 64;

    uint64_t acc2[4][4];
#pragma unroll
    for (int i = 0; i < 4; i++)
#pragma unroll
        for (int j = 0; j < 4; j++) acc2[i][j] = 0ull;

    // load indices
    const int lm  = tid >> 2;            // 0..63   (row within A tile)
    const int lkq = (tid & 3) * 4;       // 0,4,8,12 (k quad within A tile)
    int mg = blockM + lm;
    if (mg >= N_NODES) mg = N_NODES - 1; // clamp (stores are guarded)
    const float* xrow = x + (size_t)mg * NFEAT;

    for (int k0 = 0; k0 < NFEAT; k0 += 16) {
        // A tile: 64x16 fp32, stored transposed As[k][m]
        float4 av = *(const float4*)(xrow + k0 + lkq);
        As[lkq + 0][lm] = av.x;
        As[lkq + 1][lm] = av.y;
        As[lkq + 2][lm] = av.z;
        As[lkq + 3][lm] = av.w;

        // B tile: 16x128, two float4 per thread
#pragma unroll
        for (int r = 0; r < 2; r++) {
            int idx = tid + r * 256;         // 0..511
            int bk = idx >> 5;               // 0..15
            int bc = (idx & 31) * 4;         // 0..124
            *(float4*)&Bs[bk][bc] = *(const float4*)(W1 + (size_t)(k0 + bk) * NHID + bc);
        }
        __syncthreads();

#pragma unroll
        for (int kk = 0; kk < 16; kk++) {
            float4 a = *(const float4*)&As[kk][ty * 4];   // conflict-free LDS.128
            uint64_t pa[4];
            PACK2(pa[0], __float_as_uint(a.x), __float_as_uint(a.x));
            PACK2(pa[1], __float_as_uint(a.y), __float_as_uint(a.y));
            PACK2(pa[2], __float_as_uint(a.z), __float_as_uint(a.z));
            PACK2(pa[3], __float_as_uint(a.w), __float_as_uint(a.w));
            uint64_t b2[4];
            b2[0] = *(const uint64_t*)&Bs[kk][tx * 8 + 0];
            b2[1] = *(const uint64_t*)&Bs[kk][tx * 8 + 2];
            b2[2] = *(const uint64_t*)&Bs[kk][tx * 8 + 4];
            b2[3] = *(const uint64_t*)&Bs[kk][tx * 8 + 6];
#pragma unroll
            for (int i = 0; i < 4; i++) {
                FMA2(acc2[i][0], pa[i], b2[0]);
                FMA2(acc2[i][1], pa[i], b2[1]);
                FMA2(acc2[i][2], pa[i], b2[2]);
                FMA2(acc2[i][3], pa[i], b2[3]);
            }
        }
        __syncthreads();
    }

    // epilogue
#pragma unroll
    for (int i = 0; i < 4; i++) {
        int row = blockM + ty * 4 + i;
        if (row < N_NODES) {
            float v[8];
#pragma unroll
            for (int j = 0; j < 4; j++) {
                uint32_t lo, hi;
                UNPACK2(lo, hi, acc2[i][j]);
                v[2 * j]     = __uint_as_float(lo);
                v[2 * j + 1] = __uint_as_float(hi);
            }
            float* p = out + (size_t)row * NHID + tx * 8;
            *(float4*)p       = make_float4(v[0], v[1], v[2], v[3]);
            *(float4*)(p + 4) = make_float4(v[4], v[5], v[6], v[7]);
        }
    }
}

// ---------------------------------------------------------------------------
// SpMM: hout[r,:] = sum_{e in row r} vals[e] * hin[cols[e],:]   (+bias, relu)
// Warp per output row; rows[] is sorted -> binary-search the edge range.
// ---------------------------------------------------------------------------
template <bool RELU>
__global__ __launch_bounds__(256) void spmm_kernel(const int* __restrict__ rows,
                                                   const int* __restrict__ cols,
                                                   const float* __restrict__ vals,
                                                   const float* __restrict__ hin,
                                                   const float* __restrict__ bias,
                                                   float* __restrict__ hout)
{
    const int gw   = (blockIdx.x * blockDim.x + threadIdx.x) >> 5;
    const int lane = threadIdx.x & 31;
    if (gw >= N_NODES) return;

    int lo = 0, hi = N_EDGES;
    while (lo < hi) { int mid = (lo + hi) >> 1; if (rows[mid] < gw) lo = mid + 1; else hi = mid; }
    const int start = lo;
    hi = N_EDGES;
    while (lo < hi) { int mid = (lo + hi) >> 1; if (rows[mid] < gw + 1) lo = mid + 1; else hi = mid; }
    const int end = lo;

    float ax = 0.f, ay = 0.f, az = 0.f, aw = 0.f;
    int e = start;
    for (; e + 2 <= end; e += 2) {
        int   c0 = cols[e],  c1 = cols[e + 1];
        float v0 = vals[e],  v1 = vals[e + 1];
        float4 h0 = *(const float4*)(hin + (size_t)c0 * NHID + lane * 4);
        float4 h1 = *(const float4*)(hin + (size_t)c1 * NHID + lane * 4);
        ax = fmaf(v0, h0.x, ax); ay = fmaf(v0, h0.y, ay);
        az = fmaf(v0, h0.z, az); aw = fmaf(v0, h0.w, aw);
        ax = fmaf(v1, h1.x, ax); ay = fmaf(v1, h1.y, ay);
        az = fmaf(v1, h1.z, az); aw = fmaf(v1, h1.w, aw);
    }
    if (e < end) {
        int   c0 = cols[e];
        float v0 = vals[e];
        float4 h0 = *(const float4*)(hin + (size_t)c0 * NHID + lane * 4);
        ax = fmaf(v0, h0.x, ax); ay = fmaf(v0, h0.y, ay);
        az = fmaf(v0, h0.z, az); aw = fmaf(v0, h0.w, aw);
    }
    if (RELU) {
        float4 b = ((const float4*)bias)[lane];
        ax = fmaxf(ax + b.x, 0.f); ay = fmaxf(ay + b.y, 0.f);
        az = fmaxf(az + b.z, 0.f); aw = fmaxf(aw + b.w, 0.f);
    }
    *(float4*)(hout + (size_t)gw * NHID + lane * 4) = make_float4(ax, ay, az, aw);
}

// ---------------------------------------------------------------------------
// GEMM2 + log_softmax, tiled: 64 rows x 64 cols per block, 4x4 thread tile
// via f32x2. Dyn SMEM: sW[128*64] | sb[64] | sh[64*132]
// ---------------------------------------------------------------------------
__global__ __launch_bounds__(256) void gemm2_softmax_kernel(const float* __restrict__ h,
                                                            const float* __restrict__ W2,
                                                            const float* __restrict__ b2,
                                                            float* __restrict__ out)
{
    extern __shared__ char smem[];
    float* sW = (float*)smem;                        // 128*64 = 32 KB
    float* sb = (float*)(smem + 32768);              // 64
    float* sh = (float*)(smem + 33024);              // 64*132

    const int tid = threadIdx.x;
    const int r0 = blockIdx.x * 64;

    // load W2 + b2
#pragma unroll
    for (int i = 0; i < 8; ++i)
        ((float4*)sW)[tid + i * 256] = ((const float4*)W2)[tid + i * 256];
    if (tid < NCLASS) sb[tid] = b2[tid];

    // load h tile [64][128] -> sh padded 132
#pragma unroll
    for (int i = 0; i < 8; ++i) {
        int idx = tid + i * 256;              // 2048 float4
        int rr = idx >> 5, q = idx & 31;
        int rg = r0 + rr;
        if (rg >= N_NODES) rg = N_NODES - 1;
        float4 v = ((const float4*)(h + (size_t)rg * NHID))[q];
        *(float4*)(sh + rr * 132 + q * 4) = v;
    }
    __syncthreads();

    const int tx = tid & 15;       // col group: c0 = tx*4 (2 pairs)
    const int ty = tid >> 4;       // row group: r = ty*4 + i
    const int c0 = tx * 4;

    uint64_t acc2[4][2];
    {
        uint64_t bpk0 = *(const uint64_t*)(sb + c0);
        uint64_t bpk1 = *(const uint64_t*)(sb + c0 + 2);
#pragma unroll
        for (int i = 0; i < 4; ++i) { acc2[i][0] = bpk0; acc2[i][1] = bpk1; }
    }

#pragma unroll 4
    for (int k = 0; k < NHID; ++k) {
        uint64_t w0 = *(const uint64_t*)(sW + k * NCLASS + c0);
        uint64_t w1 = *(const uint64_t*)(sW + k * NCLASS + c0 + 2);
#pragma unroll
        for (int i = 0; i < 4; ++i) {
            float hv = sh[(ty * 4 + i) * 132 + k];
            uint64_t ph;
            PACK2(ph, __float_as_uint(hv), __float_as_uint(hv));
            FMA2(acc2[i][0], ph, w0);
            FMA2(acc2[i][1], ph, w1);
        }
    }

    // log-softmax across 64 cols = 16 tx-lanes (lane bits 0..3) x 4 cols
#pragma unroll
    for (int i = 0; i < 4; ++i) {
        float a[4];
        uint32_t lo, hi;
        UNPACK2(lo, hi, acc2[i][0]); a[0] = __uint_as_float(lo); a[1] = __uint_as_float(hi);
        UNPACK2(lo, hi, acc2[i][1]); a[2] = __uint_as_float(lo); a[3] = __uint_as_float(hi);

        float m = fmaxf(fmaxf(a[0], a[1]), fmaxf(a[2], a[3]));
#pragma unroll
        for (int o = 1; o < 16; o <<= 1) m = fmaxf(m, __shfl_xor_sync(0xffffffffu, m, o));
        float s = expf(a[0] - m) + expf(a[1] - m) + expf(a[2] - m) + expf(a[3] - m);
#pragma unroll
        for (int o = 1; o < 16; o <<= 1) s += __shfl_xor_sync(0xffffffffu, s, o);
        float lse = m + logf(s);

        int rg = r0 + ty * 4 + i;
        if (rg < N_NODES) {
            float4 v = make_float4(a[0] - lse, a[1] - lse, a[2] - lse, a[3] - lse);
            *(float4*)(out + (size_t)rg * NCLASS + c0) = v;
        }
    }
}

// ---------------------------------------------------------------------------
extern "C" void kernel_launch(void* const* d_in, const int* in_sizes, int n_in,
                              void* d_out, int out_size)
{
    const float* x    = (const float*)d_in[0];
    const int*   rows = (const int*)  d_in[1];
    const int*   cols = (const int*)  d_in[2];
    const float* vals = (const float*)d_in[3];
    const float* W1   = (const float*)d_in[4];
    const float* b1   = (const float*)d_in[5];
    const float* W2   = (const float*)d_in[6];
    const float* b2   = (const float*)d_in[7];
    float* out = (float*)d_out;

    float *h0, *h1;
    cudaGetSymbolAddress((void**)&h0, g_h0);
    cudaGetSymbolAddress((void**)&h1, g_h1);

    const int SMEM_G2 = 33024 + 64 * 132 * 4;   // 66816
    cudaFuncSetAttribute(gemm2_softmax_kernel, cudaFuncAttributeMaxDynamicSharedMemorySize, SMEM_G2);

    // 1) h0 = X @ W1
    gemm1_kernel<<<(N_NODES + 63) / 64, 256>>>(x, W1, h0);

    // 2) h1 = relu(A @ h0 + b1)
    const int spmm_blocks = (N_NODES * 32 + 255) / 256;
    spmm_kernel<true><<<spmm_blocks, 256>>>(rows, cols, vals, h0, b1, h1);

    // 3) h0 <- A @ h1
    spmm_kernel<false><<<spmm_blocks, 256>>>(rows, cols, vals, h1, b1, h0);

    // 4) out = logsoftmax(h0 @ W2 + b2)
    gemm2_softmax_kernel<<<(N_NODES + 63) / 64, 256, SMEM_G2>>>(h0, W2, b2, out);
}

// round 4
// speedup vs baseline: 1.6375x; 1.4534x over previous
#include <cuda_runtime.h>
#include <math.h>
#include <stdint.h>

#define N_NODES 50000
#define N_EDGES 800000
#define NFEAT   512
#define NHID    128
#define NCLASS  64

// Scratch (allocation-free)
__device__ float g_h0[(size_t)N_NODES * NHID];
__device__ float g_h1[(size_t)N_NODES * NHID];
__device__ uint16_t g_w1t_hi[NHID * NFEAT];   // W1^T hi bf16 [n][k]
__device__ uint16_t g_w1t_lo[NHID * NFEAT];   // W1^T lo bf16 [n][k]

// ---------------------------------------------------------------------------
// helpers
// ---------------------------------------------------------------------------
// pack two fp32 -> bf16x2 (lo element in low 16 bits)
__device__ __forceinline__ uint32_t pack_bf16x2(float lo, float hi) {
    uint32_t r;
    asm("cvt.rn.bf16x2.f32 %0, %1, %2;" : "=r"(r) : "f"(hi), "f"(lo));
    return r;
}
__device__ __forceinline__ float bf_lo_f32(uint32_t p) { return __uint_as_float(p << 16); }
__device__ __forceinline__ float bf_hi_f32(uint32_t p) { return __uint_as_float(p & 0xFFFF0000u); }

// m16n8k16 bf16 mma, fp32 accumulate (legacy tensor path, base ISA sm_80+)
__device__ __forceinline__ void mma_bf16(float* d, const uint32_t* a,
                                         uint32_t b0, uint32_t b1) {
    asm("mma.sync.aligned.m16n8k16.row.col.f32.bf16.bf16.f32 "
        "{%0,%1,%2,%3}, {%4,%5,%6,%7}, {%8,%9}, {%0,%1,%2,%3};"
        : "+f"(d[0]), "+f"(d[1]), "+f"(d[2]), "+f"(d[3])
        : "r"(a[0]), "r"(a[1]), "r"(a[2]), "r"(a[3]), "r"(b0), "r"(b1));
}

// ---------------------------------------------------------------------------
// prep: W1[512,128] -> W1^T bf16 hi/lo  [n][k]
// ---------------------------------------------------------------------------
__global__ void prep_w1_kernel(const float* __restrict__ W1) {
    int idx = blockIdx.x * 256 + threadIdx.x;          // over 65536/2 pairs
    if (idx >= NHID * NFEAT / 2) return;
    int n = idx >> 8;                // 512/2 = 256 pairs per n
    int k2 = (idx & 255) * 2;
    float w0 = W1[(size_t)k2 * NHID + n];
    float w1 = W1[(size_t)(k2 + 1) * NHID + n];
    uint32_t ph = pack_bf16x2(w0, w1);
    float r0 = w0 - bf_lo_f32(ph);
    float r1 = w1 - bf_hi_f32(ph);
    uint32_t pl = pack_bf16x2(r0, r1);
    *(uint32_t*)&g_w1t_hi[n * NFEAT + k2] = ph;
    *(uint32_t*)&g_w1t_lo[n * NFEAT + k2] = pl;
}

// ---------------------------------------------------------------------------
// GEMM1 via mma.sync bf16 split: out[50000,128] = x[50000,512] @ W1[512,128]
// CTA: 128x128, BK=64, 8 warps (4 M x 2 N), warp tile 32x64.
// SMEM pitch 72 bf16 (144B) -> conflict-free fragment loads.
// ---------------------------------------------------------------------------
#define LDA 72
#define SA_HI 0
#define SA_LO 9216
#define SB_HI 18432
#define SB_LO 27648
#define SMEM_G1_BYTES (36864 * 2)

__global__ __launch_bounds__(256, 2) void gemm1_mma_kernel(const float* __restrict__ x,
                                                           float* __restrict__ out)
{
    extern __shared__ uint16_t sm[];

    const int tid  = threadIdx.x;
    const int wid  = tid >> 5;
    const int lane = tid & 31;
    const int m0   = blockIdx.x * 128;

    const int wm = (wid >> 1) * 32;   // warp M base
    const int wn = (wid & 1) * 64;    // warp N base

    float acc[2][8][4];
#pragma unroll
    for (int i = 0; i < 2; i++)
#pragma unroll
        for (int j = 0; j < 8; j++)
#pragma unroll
            for (int q = 0; q < 4; q++) acc[i][j][q] = 0.f;

    // load/convert indices: each thread owns (row = tid>>1, half = tid&1) -> 32 k
    const int arow = tid >> 1;
    const int ahalf = tid & 1;
    int rg = m0 + arow;
    if (rg >= N_NODES) rg = N_NODES - 1;
    const float* xrow = x + (size_t)rg * NFEAT + ahalf * 32;
    const uint16_t* bhrow = g_w1t_hi + (size_t)arow * NFEAT + ahalf * 32;
    const uint16_t* blrow = g_w1t_lo + (size_t)arow * NFEAT + ahalf * 32;

    for (int c = 0; c < 8; ++c) {
        const int k0 = c * 64;

        // ---- A: load fp32, split hi/lo, store to smem ----
        uint32_t ph[8], pl[8];
#pragma unroll
        for (int j = 0; j < 4; ++j) {
            float4 v = *(const float4*)(xrow + k0 + j * 8);
            float4 u = *(const float4*)(xrow + k0 + j * 8 + 4);
            uint32_t p0 = pack_bf16x2(v.x, v.y);
            uint32_t p1 = pack_bf16x2(v.z, v.w);
            uint32_t p2 = pack_bf16x2(u.x, u.y);
            uint32_t p3 = pack_bf16x2(u.z, u.w);
            ph[j * 2]     = p0; ph[j * 2 + 1] = p1;
            pl[j * 2]     = pack_bf16x2(v.x - bf_lo_f32(p0), v.y - bf_hi_f32(p0));
            pl[j * 2 + 1] = pack_bf16x2(v.z - bf_lo_f32(p1), v.w - bf_hi_f32(p1));
            ph[j * 2 + 8 - 8] = p0; // (no-op, clarity)
            // store p2/p3 in next slots
            ph[j * 2 + 1] = p1;
            // handle u pair in second half of arrays:
            ph[4 + j] = 0; // placeholder, replaced below
            (void)p2; (void)p3;
        }
        // The above got convoluted; redo cleanly:
#pragma unroll
        for (int j = 0; j < 8; ++j) {
            float2 v = *(const float2*)(xrow + k0 + j * 4);
            float2 u = *(const float2*)(xrow + k0 + j * 4 + 2);
            uint32_t p0 = pack_bf16x2(v.x, v.y);
            uint32_t p1 = pack_bf16x2(u.x, u.y);
            (void)p1;
            // j covers 4 elems: pairs (v.x,v.y) and (u.x,u.y)
            ph[j] = p0;
            pl[j] = pack_bf16x2(v.x - bf_lo_f32(p0), v.y - bf_hi_f32(p0));
            if (j & 1) { } // keep loop simple
            // second pair goes into the next j slot? No — use 2 pairs per j:
        }
        // Final clean version: 8 uint pairs = 16 elems... we need 32 elems = 16 pairs.
        // Use direct loop over 16 pairs:
        {
            uint32_t H[16], L[16];
#pragma unroll
            for (int j = 0; j < 16; ++j) {
                float2 v = *(const float2*)(xrow + k0 + j * 2);
                uint32_t p = pack_bf16x2(v.x, v.y);
                H[j] = p;
                L[j] = pack_bf16x2(v.x - bf_lo_f32(p), v.y - bf_hi_f32(p));
            }
            uint16_t* dA_hi = sm + SA_HI + arow * LDA + ahalf * 32;
            uint16_t* dA_lo = sm + SA_LO + arow * LDA + ahalf * 32;
#pragma unroll
            for (int j = 0; j < 4; ++j) {
                *(uint4*)(dA_hi + j * 8) = *(uint4*)&H[j * 4];
                *(uint4*)(dA_lo + j * 8) = *(uint4*)&L[j * 4];
            }
        }

        // ---- B: copy prepped bf16 hi/lo ----
        {
            uint16_t* dB_hi = sm + SB_HI + arow * LDA + ahalf * 32;
            uint16_t* dB_lo = sm + SB_LO + arow * LDA + ahalf * 32;
#pragma unroll
            for (int j = 0; j < 4; ++j) {
                *(uint4*)(dB_hi + j * 8) = *(const uint4*)(bhrow + k0 + j * 8);
                *(uint4*)(dB_lo + j * 8) = *(const uint4*)(blrow + k0 + j * 8);
            }
        }
        __syncthreads();

        // ---- MMA: 4 k-steps of 16 ----
#pragma unroll
        for (int ks = 0; ks < 4; ++ks) {
            const int kk = ks * 16;
            uint32_t a_hi[2][4], a_lo[2][4];
#pragma unroll
            for (int mt = 0; mt < 2; ++mt) {
                int r = wm + mt * 16 + (lane >> 2);
                int cc = kk + (lane & 3) * 2;
                a_hi[mt][0] = *(const uint32_t*)(sm + SA_HI + r * LDA + cc);
                a_hi[mt][1] = *(const uint32_t*)(sm + SA_HI + (r + 8) * LDA + cc);
                a_hi[mt][2] = *(const uint32_t*)(sm + SA_HI + r * LDA + cc + 8);
                a_hi[mt][3] = *(const uint32_t*)(sm + SA_HI + (r + 8) * LDA + cc + 8);
                a_lo[mt][0] = *(const uint32_t*)(sm + SA_LO + r * LDA + cc);
                a_lo[mt][1] = *(const uint32_t*)(sm + SA_LO + (r + 8) * LDA + cc);
                a_lo[mt][2] = *(const uint32_t*)(sm + SA_LO + r * LDA + cc + 8);
                a_lo[mt][3] = *(const uint32_t*)(sm + SA_LO + (r + 8) * LDA + cc + 8);
            }
#pragma unroll
            for (int nt = 0; nt < 8; ++nt) {
                int n = wn + nt * 8 + (lane >> 2);
                int kq = kk + (lane & 3) * 2;
                uint32_t bh0 = *(const uint32_t*)(sm + SB_HI + n * LDA + kq);
                uint32_t bh1 = *(const uint32_t*)(sm + SB_HI + n * LDA + kq + 8);
                uint32_t bl0 = *(const uint32_t*)(sm + SB_LO + n * LDA + kq);
                uint32_t bl1 = *(const uint32_t*)(sm + SB_LO + n * LDA + kq + 8);
#pragma unroll
                for (int mt = 0; mt < 2; ++mt) {
                    mma_bf16(acc[mt][nt], a_hi[mt], bh0, bh1);
                    mma_bf16(acc[mt][nt], a_hi[mt], bl0, bl1);
                    mma_bf16(acc[mt][nt], a_lo[mt], bh0, bh1);
                }
            }
        }
        __syncthreads();
    }

    // ---- epilogue: direct stores, float2 per (row, colpair) ----
#pragma unroll
    for (int mt = 0; mt < 2; ++mt) {
        int r0 = m0 + wm + mt * 16 + (lane >> 2);
        int r1 = r0 + 8;
#pragma unroll
        for (int nt = 0; nt < 8; ++nt) {
            int cc = wn + nt * 8 + (lane & 3) * 2;
            if (r0 < N_NODES)
                *(float2*)(out + (size_t)r0 * NHID + cc) = make_float2(acc[mt][nt][0], acc[mt][nt][1]);
            if (r1 < N_NODES)
                *(float2*)(out + (size_t)r1 * NHID + cc) = make_float2(acc[mt][nt][2], acc[mt][nt][3]);
        }
    }
}

// ---------------------------------------------------------------------------
// SpMM: warp per row, sorted-COO binary search
// ---------------------------------------------------------------------------
template <bool RELU>
__global__ __launch_bounds__(256) void spmm_kernel(const int* __restrict__ rows,
                                                   const int* __restrict__ cols,
                                                   const float* __restrict__ vals,
                                                   const float* __restrict__ hin,
                                                   const float* __restrict__ bias,
                                                   float* __restrict__ hout)
{
    const int gw   = (blockIdx.x * blockDim.x + threadIdx.x) >> 5;
    const int lane = threadIdx.x & 31;
    if (gw >= N_NODES) return;

    int lo = 0, hi = N_EDGES;
    while (lo < hi) { int mid = (lo + hi) >> 1; if (rows[mid] < gw) lo = mid + 1; else hi = mid; }
    const int start = lo;
    hi = N_EDGES;
    while (lo < hi) { int mid = (lo + hi) >> 1; if (rows[mid] < gw + 1) lo = mid + 1; else hi = mid; }
    const int end = lo;

    float ax = 0.f, ay = 0.f, az = 0.f, aw = 0.f;
    int e = start;
    for (; e + 2 <= end; e += 2) {
        int   c0 = cols[e],  c1 = cols[e + 1];
        float v0 = vals[e],  v1 = vals[e + 1];
        float4 h0 = *(const float4*)(hin + (size_t)c0 * NHID + lane * 4);
        float4 h1 = *(const float4*)(hin + (size_t)c1 * NHID + lane * 4);
        ax = fmaf(v0, h0.x, ax); ay = fmaf(v0, h0.y, ay);
        az = fmaf(v0, h0.z, az); aw = fmaf(v0, h0.w, aw);
        ax = fmaf(v1, h1.x, ax); ay = fmaf(v1, h1.y, ay);
        az = fmaf(v1, h1.z, az); aw = fmaf(v1, h1.w, aw);
    }
    if (e < end) {
        int   c0 = cols[e];
        float v0 = vals[e];
        float4 h0 = *(const float4*)(hin + (size_t)c0 * NHID + lane * 4);
        ax = fmaf(v0, h0.x, ax); ay = fmaf(v0, h0.y, ay);
        az = fmaf(v0, h0.z, az); aw = fmaf(v0, h0.w, aw);
    }
    if (RELU) {
        float4 b = ((const float4*)bias)[lane];
        ax = fmaxf(ax + b.x, 0.f); ay = fmaxf(ay + b.y, 0.f);
        az = fmaxf(az + b.z, 0.f); aw = fmaxf(aw + b.w, 0.f);
    }
    *(float4*)(hout + (size_t)gw * NHID + lane * 4) = make_float4(ax, ay, az, aw);
}

// ---------------------------------------------------------------------------
// GEMM2 + log_softmax, tiled 64x64, 4x4 thread tile via f32x2
// ---------------------------------------------------------------------------
#define FMA2(acc, a, b) \
    asm("fma.rn.f32x2 %0, %1, %2, %0;" : "+l"(acc) : "l"(a), "l"(b))
#define PACK2(out, lo, hi) \
    asm("mov.b64 %0, {%1, %2};" : "=l"(out) : "r"(lo), "r"(hi))
#define UNPACK2(lo, hi, in) \
    asm("mov.b64 {%0, %1}, %2;" : "=r"(lo), "=r"(hi) : "l"(in))

__global__ __launch_bounds__(256) void gemm2_softmax_kernel(const float* __restrict__ h,
                                                            const float* __restrict__ W2,
                                                            const float* __restrict__ b2,
                                                            float* __restrict__ out)
{
    extern __shared__ char smem[];
    float* sW = (float*)smem;                        // 128*64 = 32 KB
    float* sb = (float*)(smem + 32768);              // 64
    float* sh = (float*)(smem + 33024);              // 64*132

    const int tid = threadIdx.x;
    const int r0 = blockIdx.x * 64;

#pragma unroll
    for (int i = 0; i < 8; ++i)
        ((float4*)sW)[tid + i * 256] = ((const float4*)W2)[tid + i * 256];
    if (tid < NCLASS) sb[tid] = b2[tid];

#pragma unroll
    for (int i = 0; i < 8; ++i) {
        int idx = tid + i * 256;
        int rr = idx >> 5, q = idx & 31;
        int rg = r0 + rr;
        if (rg >= N_NODES) rg = N_NODES - 1;
        float4 v = ((const float4*)(h + (size_t)rg * NHID))[q];
        *(float4*)(sh + rr * 132 + q * 4) = v;
    }
    __syncthreads();

    const int tx = tid & 15;
    const int ty = tid >> 4;
    const int c0 = tx * 4;

    uint64_t acc2[4][2];
    {
        uint64_t bpk0 = *(const uint64_t*)(sb + c0);
        uint64_t bpk1 = *(const uint64_t*)(sb + c0 + 2);
#pragma unroll
        for (int i = 0; i < 4; ++i) { acc2[i][0] = bpk0; acc2[i][1] = bpk1; }
    }

#pragma unroll 4
    for (int k = 0; k < NHID; ++k) {
        uint64_t w0 = *(const uint64_t*)(sW + k * NCLASS + c0);
        uint64_t w1 = *(const uint64_t*)(sW + k * NCLASS + c0 + 2);
#pragma unroll
        for (int i = 0; i < 4; ++i) {
            float hv = sh[(ty * 4 + i) * 132 + k];
            uint64_t ph;
            PACK2(ph, __float_as_uint(hv), __float_as_uint(hv));
            FMA2(acc2[i][0], ph, w0);
            FMA2(acc2[i][1], ph, w1);
        }
    }

#pragma unroll
    for (int i = 0; i < 4; ++i) {
        float a[4];
        uint32_t lo, hi;
        UNPACK2(lo, hi, acc2[i][0]); a[0] = __uint_as_float(lo); a[1] = __uint_as_float(hi);
        UNPACK2(lo, hi, acc2[i][1]); a[2] = __uint_as_float(lo); a[3] = __uint_as_float(hi);

        float m = fmaxf(fmaxf(a[0], a[1]), fmaxf(a[2], a[3]));
#pragma unroll
        for (int o = 1; o < 16; o <<= 1) m = fmaxf(m, __shfl_xor_sync(0xffffffffu, m, o));
        float s = expf(a[0] - m) + expf(a[1] - m) + expf(a[2] - m) + expf(a[3] - m);
#pragma unroll
        for (int o = 1; o < 16; o <<= 1) s += __shfl_xor_sync(0xffffffffu, s, o);
        float lse = m + logf(s);

        int rg = r0 + ty * 4 + i;
        if (rg < N_NODES) {
            float4 v = make_float4(a[0] - lse, a[1] - lse, a[2] - lse, a[3] - lse);
            *(float4*)(out + (size_t)rg * NCLASS + c0) = v;
        }
    }
}

// ---------------------------------------------------------------------------
extern "C" void kernel_launch(void* const* d_in, const int* in_sizes, int n_in,
                              void* d_out, int out_size)
{
    const float* x    = (const float*)d_in[0];
    const int*   rows = (const int*)  d_in[1];
    const int*   cols = (const int*)  d_in[2];
    const float* vals = (const float*)d_in[3];
    const float* W1   = (const float*)d_in[4];
    const float* b1   = (const float*)d_in[5];
    const float* W2   = (const float*)d_in[6];
    const float* b2   = (const float*)d_in[7];
    float* out = (float*)d_out;

    float *h0, *h1;
    cudaGetSymbolAddress((void**)&h0, g_h0);
    cudaGetSymbolAddress((void**)&h1, g_h1);

    const int SMEM_G2 = 33024 + 64 * 132 * 4;
    cudaFuncSetAttribute(gemm1_mma_kernel, cudaFuncAttributeMaxDynamicSharedMemorySize, SMEM_G1_BYTES);
    cudaFuncSetAttribute(gemm2_softmax_kernel, cudaFuncAttributeMaxDynamicSharedMemorySize, SMEM_G2);

    // 0) prep W1^T bf16 hi/lo
    prep_w1_kernel<<<(NHID * NFEAT / 2 + 255) / 256, 256>>>(W1);

    // 1) h0 = X @ W1  (mma.sync bf16, 3-term split)
    gemm1_mma_kernel<<<(N_NODES + 127) / 128, 256, SMEM_G1_BYTES>>>(x, h0);

    // 2) h1 = relu(A @ h0 + b1)
    const int spmm_blocks = (N_NODES * 32 + 255) / 256;
    spmm_kernel<true><<<spmm_blocks, 256>>>(rows, cols, vals, h0, b1, h1);

    // 3) h0 <- A @ h1
    spmm_kernel<false><<<spmm_blocks, 256>>>(rows, cols, vals, h1, b1, h0);

    // 4) out = logsoftmax(h0 @ W2 + b2)
    gemm2_softmax_kernel<<<(N_NODES + 63) / 64, 256, SMEM_G2>>>(h0, W2, b2, out);
}

// round 5
// speedup vs baseline: 2.3628x; 1.4430x over previous
#include <cuda_runtime.h>
#include <math.h>
#include <stdint.h>

#define N_NODES 50000
#define N_EDGES 800000
#define NFEAT   512
#define NHID    128
#define NCLASS  64

// Scratch (allocation-free)
__device__ float g_h0[(size_t)N_NODES * NHID];
__device__ float g_h1[(size_t)N_NODES * NHID];
__device__ uint16_t g_w1t_hi[NHID * NFEAT];   // W1^T hi bf16 [n][k]
__device__ uint16_t g_w1t_lo[NHID * NFEAT];   // W1^T lo bf16 [n][k]
__device__ int g_rowptr[N_NODES + 1];

// ---------------------------------------------------------------------------
// helpers
// ---------------------------------------------------------------------------
__device__ __forceinline__ uint32_t smem_u32(const void* p) {
    uint32_t a;
    asm("{ .reg .u64 t; cvta.to.shared.u64 t, %1; cvt.u32.u64 %0, t; }" : "=r"(a) : "l"(p));
    return a;
}
// pack two fp32 -> bf16x2 (first arg in low 16 bits)
__device__ __forceinline__ uint32_t pack_bf16x2(float lo, float hi) {
    uint32_t r;
    asm("cvt.rn.bf16x2.f32 %0, %1, %2;" : "=r"(r) : "f"(hi), "f"(lo));
    return r;
}
__device__ __forceinline__ float bf_lo_f32(uint32_t p) { return __uint_as_float(p << 16); }
__device__ __forceinline__ float bf_hi_f32(uint32_t p) { return __uint_as_float(p & 0xFFFF0000u); }

__device__ __forceinline__ void mma_bf16(float* d, const uint32_t* a,
                                         uint32_t b0, uint32_t b1) {
    asm("mma.sync.aligned.m16n8k16.row.col.f32.bf16.bf16.f32 "
        "{%0,%1,%2,%3}, {%4,%5,%6,%7}, {%8,%9}, {%0,%1,%2,%3};"
        : "+f"(d[0]), "+f"(d[1]), "+f"(d[2]), "+f"(d[3])
        : "r"(a[0]), "r"(a[1]), "r"(a[2]), "r"(a[3]), "r"(b0), "r"(b1));
}
__device__ __forceinline__ void cp_async16(uint32_t dst, const void* src) {
    asm volatile("cp.async.cg.shared.global [%0], [%1], 16;" :: "r"(dst), "l"(src));
}
#define CP_COMMIT() asm volatile("cp.async.commit_group;" ::: "memory")
#define CP_WAIT0()  asm volatile("cp.async.wait_group 0;" ::: "memory")

// ---------------------------------------------------------------------------
// prep kernels
// ---------------------------------------------------------------------------
__global__ void prep_w1_kernel(const float* __restrict__ W1) {
    int idx = blockIdx.x * 256 + threadIdx.x;
    if (idx >= NHID * NFEAT / 2) return;
    int n = idx >> 8;
    int k2 = (idx & 255) * 2;
    float w0 = W1[(size_t)k2 * NHID + n];
    float w1 = W1[(size_t)(k2 + 1) * NHID + n];
    uint32_t ph = pack_bf16x2(w0, w1);
    uint32_t pl = pack_bf16x2(w0 - bf_lo_f32(ph), w1 - bf_hi_f32(ph));
    *(uint32_t*)&g_w1t_hi[n * NFEAT + k2] = ph;
    *(uint32_t*)&g_w1t_lo[n * NFEAT + k2] = pl;
}

__global__ void rowptr_kernel(const int* __restrict__ rows) {
    int e = blockIdx.x * 256 + threadIdx.x;
    if (e >= N_EDGES) return;
    int r = rows[e];
    int rp = (e == 0) ? -1 : rows[e - 1];
    for (int q = rp + 1; q <= r; ++q) g_rowptr[q] = e;
    if (e == N_EDGES - 1)
        for (int q = r + 1; q <= N_NODES; ++q) g_rowptr[q] = N_EDGES;
}

// ---------------------------------------------------------------------------
// GEMM1 via mma.sync bf16 split, double-buffered + cp.async.
// CTA 128x128, BK=64, 8 warps (4M x 2N), warp tile 32x64. Pitch 72 bf16.
// ---------------------------------------------------------------------------
#define LDA 72
#define SA_HI 0
#define SA_LO 9216
#define SB_HI 18432
#define SB_LO 27648
#define BUFE  36864                           // elems per buffer
#define SMEM_G1_BYTES (2 * BUFE * 2)          // 147456 B

__global__ __launch_bounds__(256, 1) void gemm1_mma_kernel(const float* __restrict__ x,
                                                           float* __restrict__ out)
{
    extern __shared__ uint16_t sm[];
    const uint32_t smb = smem_u32(sm);

    const int tid  = threadIdx.x;
    const int wid  = tid >> 5;
    const int lane = tid & 31;
    const int m0   = blockIdx.x * 128;
    const int wm = (wid >> 1) * 32;
    const int wn = (wid & 1) * 64;

    float acc[2][8][4];
#pragma unroll
    for (int i = 0; i < 2; i++)
#pragma unroll
        for (int j = 0; j < 8; j++)
#pragma unroll
            for (int q = 0; q < 4; q++) acc[i][j][q] = 0.f;

    const int arow = tid >> 1;
    const int ahalf = tid & 1;
    int rg = m0 + arow;
    if (rg >= N_NODES) rg = N_NODES - 1;
    const float* xrow = x + (size_t)rg * NFEAT + ahalf * 32;
    const uint16_t* bhrow = g_w1t_hi + (size_t)arow * NFEAT + ahalf * 32;
    const uint16_t* blrow = g_w1t_lo + (size_t)arow * NFEAT + ahalf * 32;
    const int dstA = arow * LDA + ahalf * 32;   // element offset within region

    float4 xa[8];

#define COPY_B(c, buf) do {                                                   \
        uint32_t dh = smb + ((buf) * BUFE + SB_HI + dstA) * 2;                \
        uint32_t dl = smb + ((buf) * BUFE + SB_LO + dstA) * 2;                \
        _Pragma("unroll")                                                     \
        for (int j = 0; j < 4; ++j) {                                         \
            cp_async16(dh + j * 16, bhrow + (c) * 64 + j * 8);                \
            cp_async16(dl + j * 16, blrow + (c) * 64 + j * 8);                \
        }                                                                     \
        CP_COMMIT();                                                          \
    } while (0)

#define LOAD_A(c) do {                                                        \
        _Pragma("unroll")                                                     \
        for (int j = 0; j < 8; ++j)                                           \
            xa[j] = *(const float4*)(xrow + (c) * 64 + j * 4);                \
    } while (0)

#define CONV_STORE_A(buf) do {                                                \
        uint32_t H[16], L[16];                                                \
        _Pragma("unroll")                                                     \
        for (int j = 0; j < 8; ++j) {                                         \
            uint32_t p0 = pack_bf16x2(xa[j].x, xa[j].y);                      \
            uint32_t p1 = pack_bf16x2(xa[j].z, xa[j].w);                      \
            H[2*j]   = p0;                                                    \
            H[2*j+1] = p1;                                                    \
            L[2*j]   = pack_bf16x2(xa[j].x - bf_lo_f32(p0), xa[j].y - bf_hi_f32(p0)); \
            L[2*j+1] = pack_bf16x2(xa[j].z - bf_lo_f32(p1), xa[j].w - bf_hi_f32(p1)); \
        }                                                                     \
        uint16_t* dh = sm + (buf) * BUFE + SA_HI + dstA;                      \
        uint16_t* dl = sm + (buf) * BUFE + SA_LO + dstA;                      \
        _Pragma("unroll")                                                     \
        for (int j = 0; j < 4; ++j) {                                         \
            *(uint4*)(dh + j * 8) = *(uint4*)&H[j * 4];                       \
            *(uint4*)(dl + j * 8) = *(uint4*)&L[j * 4];                       \
        }                                                                     \
    } while (0)

    // prologue: stage chunk 0 into buffer 0
    COPY_B(0, 0);
    LOAD_A(0);
    CONV_STORE_A(0);
    CP_WAIT0();
    __syncthreads();

    for (int c = 0; c < 8; ++c) {
        const int cur = c & 1, nxt = cur ^ 1;
        if (c < 7) { COPY_B(c + 1, nxt); LOAD_A(c + 1); }

        // ---- MMA on buffer cur ----
        const uint16_t* base = sm + cur * BUFE;
#pragma unroll
        for (int ks = 0; ks < 4; ++ks) {
            const int kk = ks * 16;
            uint32_t a_hi[2][4], a_lo[2][4];
#pragma unroll
            for (int mt = 0; mt < 2; ++mt) {
                int r = wm + mt * 16 + (lane >> 2);
                int cc = kk + (lane & 3) * 2;
                a_hi[mt][0] = *(const uint32_t*)(base + SA_HI + r * LDA + cc);
                a_hi[mt][1] = *(const uint32_t*)(base + SA_HI + (r + 8) * LDA + cc);
                a_hi[mt][2] = *(const uint32_t*)(base + SA_HI + r * LDA + cc + 8);
                a_hi[mt][3] = *(const uint32_t*)(base + SA_HI + (r + 8) * LDA + cc + 8);
                a_lo[mt][0] = *(const uint32_t*)(base + SA_LO + r * LDA + cc);
                a_lo[mt][1] = *(const uint32_t*)(base + SA_LO + (r + 8) * LDA + cc);
                a_lo[mt][2] = *(const uint32_t*)(base + SA_LO + r * LDA + cc + 8);
                a_lo[mt][3] = *(const uint32_t*)(base + SA_LO + (r + 8) * LDA + cc + 8);
            }
#pragma unroll
            for (int nt = 0; nt < 8; ++nt) {
                int n = wn + nt * 8 + (lane >> 2);
                int kq = kk + (lane & 3) * 2;
                uint32_t bh0 = *(const uint32_t*)(base + SB_HI + n * LDA + kq);
                uint32_t bh1 = *(const uint32_t*)(base + SB_HI + n * LDA + kq + 8);
                uint32_t bl0 = *(const uint32_t*)(base + SB_LO + n * LDA + kq);
                uint32_t bl1 = *(const uint32_t*)(base + SB_LO + n * LDA + kq + 8);
#pragma unroll
                for (int mt = 0; mt < 2; ++mt) {
                    mma_bf16(acc[mt][nt], a_hi[mt], bh0, bh1);
                    mma_bf16(acc[mt][nt], a_hi[mt], bl0, bl1);
                    mma_bf16(acc[mt][nt], a_lo[mt], bh0, bh1);
                }
            }
        }

        if (c < 7) { CONV_STORE_A(nxt); CP_WAIT0(); }
        __syncthreads();
    }

    // epilogue
#pragma unroll
    for (int mt = 0; mt < 2; ++mt) {
        int r0 = m0 + wm + mt * 16 + (lane >> 2);
        int r1 = r0 + 8;
#pragma unroll
        for (int nt = 0; nt < 8; ++nt) {
            int cc = wn + nt * 8 + (lane & 3) * 2;
            if (r0 < N_NODES)
                *(float2*)(out + (size_t)r0 * NHID + cc) = make_float2(acc[mt][nt][0], acc[mt][nt][1]);
            if (r1 < N_NODES)
                *(float2*)(out + (size_t)r1 * NHID + cc) = make_float2(acc[mt][nt][2], acc[mt][nt][3]);
        }
    }
}

// ---------------------------------------------------------------------------
// SpMM: warp per row, row_ptr lookup (no binary search), 4-edge unroll.
// ---------------------------------------------------------------------------
template <bool RELU>
__global__ __launch_bounds__(256) void spmm_kernel(const int* __restrict__ cols,
                                                   const float* __restrict__ vals,
                                                   const float* __restrict__ hin,
                                                   const float* __restrict__ bias,
                                                   float* __restrict__ hout)
{
    const int gw   = (blockIdx.x * blockDim.x + threadIdx.x) >> 5;
    const int lane = threadIdx.x & 31;
    if (gw >= N_NODES) return;

    const int start = g_rowptr[gw];
    const int end   = g_rowptr[gw + 1];

    float ax = 0.f, ay = 0.f, az = 0.f, aw = 0.f;
    int e = start;
    for (; e + 4 <= end; e += 4) {
        int   c0 = cols[e],     c1 = cols[e + 1], c2 = cols[e + 2], c3 = cols[e + 3];
        float v0 = vals[e],     v1 = vals[e + 1], v2 = vals[e + 2], v3 = vals[e + 3];
        float4 h0 = *(const float4*)(hin + (size_t)c0 * NHID + lane * 4);
        float4 h1 = *(const float4*)(hin + (size_t)c1 * NHID + lane * 4);
        float4 h2 = *(const float4*)(hin + (size_t)c2 * NHID + lane * 4);
        float4 h3 = *(const float4*)(hin + (size_t)c3 * NHID + lane * 4);
        ax = fmaf(v0, h0.x, ax); ay = fmaf(v0, h0.y, ay);
        az = fmaf(v0, h0.z, az); aw = fmaf(v0, h0.w, aw);
        ax = fmaf(v1, h1.x, ax); ay = fmaf(v1, h1.y, ay);
        az = fmaf(v1, h1.z, az); aw = fmaf(v1, h1.w, aw);
        ax = fmaf(v2, h2.x, ax); ay = fmaf(v2, h2.y, ay);
        az = fmaf(v2, h2.z, az); aw = fmaf(v2, h2.w, aw);
        ax = fmaf(v3, h3.x, ax); ay = fmaf(v3, h3.y, ay);
        az = fmaf(v3, h3.z, az); aw = fmaf(v3, h3.w, aw);
    }
    for (; e < end; ++e) {
        int   c0 = cols[e];
        float v0 = vals[e];
        float4 h0 = *(const float4*)(hin + (size_t)c0 * NHID + lane * 4);
        ax = fmaf(v0, h0.x, ax); ay = fmaf(v0, h0.y, ay);
        az = fmaf(v0, h0.z, az); aw = fmaf(v0, h0.w, aw);
    }
    if (RELU) {
        float4 b = ((const float4*)bias)[lane];
        ax = fmaxf(ax + b.x, 0.f); ay = fmaxf(ay + b.y, 0.f);
        az = fmaxf(az + b.z, 0.f); aw = fmaxf(aw + b.w, 0.f);
    }
    *(float4*)(hout + (size_t)gw * NHID + lane * 4) = make_float4(ax, ay, az, aw);
}

// ---------------------------------------------------------------------------
// GEMM2 + log_softmax, tiled 64x64, 4x4 thread tile via f32x2
// ---------------------------------------------------------------------------
#define FMA2(acc, a, b) \
    asm("fma.rn.f32x2 %0, %1, %2, %0;" : "+l"(acc) : "l"(a), "l"(b))
#define PACK2(out, lo, hi) \
    asm("mov.b64 %0, {%1, %2};" : "=l"(out) : "r"(lo), "r"(hi))
#define UNPACK2(lo, hi, in) \
    asm("mov.b64 {%0, %1}, %2;" : "=r"(lo), "=r"(hi) : "l"(in))

__global__ __launch_bounds__(256) void gemm2_softmax_kernel(const float* __restrict__ h,
                                                            const float* __restrict__ W2,
                                                            const float* __restrict__ b2,
                                                            float* __restrict__ out)
{
    extern __shared__ char smem[];
    float* sW = (float*)smem;                        // 32 KB
    float* sb = (float*)(smem + 32768);
    float* sh = (float*)(smem + 33024);              // 64*132

    const int tid = threadIdx.x;
    const int r0 = blockIdx.x * 64;

#pragma unroll
    for (int i = 0; i < 8; ++i)
        ((float4*)sW)[tid + i * 256] = ((const float4*)W2)[tid + i * 256];
    if (tid < NCLASS) sb[tid] = b2[tid];

#pragma unroll
    for (int i = 0; i < 8; ++i) {
        int idx = tid + i * 256;
        int rr = idx >> 5, q = idx & 31;
        int rg = r0 + rr;
        if (rg >= N_NODES) rg = N_NODES - 1;
        float4 v = ((const float4*)(h + (size_t)rg * NHID))[q];
        *(float4*)(sh + rr * 132 + q * 4) = v;
    }
    __syncthreads();

    const int tx = tid & 15;
    const int ty = tid >> 4;
    const int c0 = tx * 4;

    uint64_t acc2[4][2];
    {
        uint64_t bpk0 = *(const uint64_t*)(sb + c0);
        uint64_t bpk1 = *(const uint64_t*)(sb + c0 + 2);
#pragma unroll
        for (int i = 0; i < 4; ++i) { acc2[i][0] = bpk0; acc2[i][1] = bpk1; }
    }

#pragma unroll 4
    for (int k = 0; k < NHID; ++k) {
        uint64_t w0 = *(const uint64_t*)(sW + k * NCLASS + c0);
        uint64_t w1 = *(const uint64_t*)(sW + k * NCLASS + c0 + 2);
#pragma unroll
        for (int i = 0; i < 4; ++i) {
            float hv = sh[(ty * 4 + i) * 132 + k];
            uint64_t ph;
            PACK2(ph, __float_as_uint(hv), __float_as_uint(hv));
            FMA2(acc2[i][0], ph, w0);
            FMA2(acc2[i][1], ph, w1);
        }
    }

#pragma unroll
    for (int i = 0; i < 4; ++i) {
        float a[4];
        uint32_t lo, hi;
        UNPACK2(lo, hi, acc2[i][0]); a[0] = __uint_as_float(lo); a[1] = __uint_as_float(hi);
        UNPACK2(lo, hi, acc2[i][1]); a[2] = __uint_as_float(lo); a[3] = __uint_as_float(hi);

        float m = fmaxf(fmaxf(a[0], a[1]), fmaxf(a[2], a[3]));
#pragma unroll
        for (int o = 1; o < 16; o <<= 1) m = fmaxf(m, __shfl_xor_sync(0xffffffffu, m, o));
        float s = expf(a[0] - m) + expf(a[1] - m) + expf(a[2] - m) + expf(a[3] - m);
#pragma unroll
        for (int o = 1; o < 16; o <<= 1) s += __shfl_xor_sync(0xffffffffu, s, o);
        float lse = m + logf(s);

        int rg = r0 + ty * 4 + i;
        if (rg < N_NODES) {
            float4 v = make_float4(a[0] - lse, a[1] - lse, a[2] - lse, a[3] - lse);
            *(float4*)(out + (size_t)rg * NCLASS + c0) = v;
        }
    }
}

// ---------------------------------------------------------------------------
extern "C" void kernel_launch(void* const* d_in, const int* in_sizes, int n_in,
                              void* d_out, int out_size)
{
    const float* x    = (const float*)d_in[0];
    const int*   rows = (const int*)  d_in[1];
    const int*   cols = (const int*)  d_in[2];
    const float* vals = (const float*)d_in[3];
    const float* W1   = (const float*)d_in[4];
    const float* b1   = (const float*)d_in[5];
    const float* W2   = (const float*)d_in[6];
    const float* b2   = (const float*)d_in[7];
    float* out = (float*)d_out;

    float *h0, *h1;
    cudaGetSymbolAddress((void**)&h0, g_h0);
    cudaGetSymbolAddress((void**)&h1, g_h1);

    const int SMEM_G2 = 33024 + 64 * 132 * 4;
    cudaFuncSetAttribute(gemm1_mma_kernel, cudaFuncAttributeMaxDynamicSharedMemorySize, SMEM_G1_BYTES);
    cudaFuncSetAttribute(gemm2_softmax_kernel, cudaFuncAttributeMaxDynamicSharedMemorySize, SMEM_G2);

    // 0) prep: W1^T bf16 hi/lo, row_ptr
    prep_w1_kernel<<<(NHID * NFEAT / 2 + 255) / 256, 256>>>(W1);
    rowptr_kernel<<<(N_EDGES + 255) / 256, 256>>>(rows);

    // 1) h0 = X @ W1  (mma.sync bf16, 3-term split, pipelined)
    gemm1_mma_kernel<<<(N_NODES + 127) / 128, 256, SMEM_G1_BYTES>>>(x, h0);

    // 2) h1 = relu(A @ h0 + b1)
    const int spmm_blocks = (N_NODES * 32 + 255) / 256;
    spmm_kernel<true><<<spmm_blocks, 256>>>(cols, vals, h0, b1, h1);

    // 3) h0 <- A @ h1
    spmm_kernel<false><<<spmm_blocks, 256>>>(cols, vals, h1, b1, h0);

    // 4) out = logsoftmax(h0 @ W2 + b2)
    gemm2_softmax_kernel<<<(N_NODES + 63) / 64, 256, SMEM_G2>>>(h0, W2, b2, out);
}